// round 17
// baseline (speedup 1.0000x reference)
#include <cuda_runtime.h>

#define NN   16384
#define EE   524288
#define DIN  256
#define DOUT 128
#define X_ELEMS (NN * DOUT)

#define NQCHUNK  65536    // 65536 x 1024 f4 x 16B = 1,073,741,824 B = all of A
#define CHUNK_F4 1024     // 16KB per warp-claim

// Scratch (no allocations allowed).
__device__ float    g_part[2 * NN * DOUT];   // split-K partials (16.8 MB)
__device__ float    g_s[EE];
__device__ float    g_ssum[NN];
__device__ int      g_cnt[NN];
__device__ float    g_sq[NN];
__device__ unsigned g_zctr;                  // zero queue (reset by scatter)

// Split-K GEMM: 256 blocks; block b -> tile (b>>1), K-half (b&1).
// Triggers PDL at entry so combine+score can launch immediately.
__global__ __launch_bounds__(256) void gemm_split_kernel(const float* __restrict__ In,
                                                         const float* __restrict__ W) {
#if __CUDA_ARCH__ >= 900
    cudaTriggerProgrammaticLaunchCompletion();
#endif
    __shared__ __align__(16) float Ast[32][132];
    __shared__ __align__(16) float Bs[32][128];

    const int tid  = threadIdx.x;
    const int tile = blockIdx.x >> 1;
    const int kh   = blockIdx.x & 1;
    const int brow = tile * 128;
    const int kbeg = kh * 128;
    const int tx   = tid & 15;
    const int ty   = tid >> 4;

    // kh==0 block of each tile inits softmax accumulators for its 128 rows
    if (kh == 0 && tid < 128) {
        g_ssum[brow + tid] = 0.0f;
        g_cnt[brow + tid]  = 0;
    }

    float acc[8][8];
#pragma unroll
    for (int i = 0; i < 8; i++)
#pragma unroll
        for (int j = 0; j < 8; j++) acc[i][j] = 0.0f;

    for (int k0 = kbeg; k0 < kbeg + 128; k0 += 32) {
#pragma unroll
        for (int i = 0; i < 4; i++) {
            int f  = tid + i * 256;
            int r  = f >> 3;
            int c4 = f & 7;
            float4 v = *(const float4*)(In + (size_t)(brow + r) * DIN + k0 + c4 * 4);
            Ast[c4 * 4 + 0][r] = v.x;
            Ast[c4 * 4 + 1][r] = v.y;
            Ast[c4 * 4 + 2][r] = v.z;
            Ast[c4 * 4 + 3][r] = v.w;
        }
#pragma unroll
        for (int i = 0; i < 4; i++) {
            int f = tid + i * 256;
            int r = f >> 5;
            int c = (f & 31) * 4;
            *(float4*)&Bs[r][c] = *(const float4*)(W + (size_t)(k0 + r) * DOUT + c);
        }
        __syncthreads();
#pragma unroll 4
        for (int k = 0; k < 32; k++) {
            float4 a0 = *(float4*)&Ast[k][ty * 8];
            float4 a1 = *(float4*)&Ast[k][ty * 8 + 4];
            float4 b0 = *(float4*)&Bs[k][tx * 8];
            float4 b1 = *(float4*)&Bs[k][tx * 8 + 4];
            float a[8] = {a0.x, a0.y, a0.z, a0.w, a1.x, a1.y, a1.z, a1.w};
            float b[8] = {b0.x, b0.y, b0.z, b0.w, b1.x, b1.y, b1.z, b1.w};
#pragma unroll
            for (int i = 0; i < 8; i++)
#pragma unroll
                for (int j = 0; j < 8; j++)
                    acc[i][j] = fmaf(a[i], b[j], acc[i][j]);
        }
        __syncthreads();
    }

    float* P = g_part + (size_t)kh * NN * DOUT;
#pragma unroll
    for (int i = 0; i < 8; i++) {
        int r = brow + ty * 8 + i;
        float4 o0 = {acc[i][0], acc[i][1], acc[i][2], acc[i][3]};
        float4 o1 = {acc[i][4], acc[i][5], acc[i][6], acc[i][7]};
        *(float4*)(P + (size_t)r * DOUT + tx * 8)     = o0;
        *(float4*)(P + (size_t)r * DOUT + tx * 8 + 4) = o1;
    }
}

// Combine partials -> X + per-row squared norm. Small grid (128 blocks) so
// its parked pre-sync blocks can't starve score of thread slots. Triggers
// PDL at entry so score launches immediately too.
__global__ __launch_bounds__(256) void combine_kernel(float* __restrict__ X) {
#if __CUDA_ARCH__ >= 900
    cudaTriggerProgrammaticLaunchCompletion();
    cudaGridDependencySynchronize();   // wait for gemm's g_part
#endif
    int w0   = (blockIdx.x * 256 + threadIdx.x) >> 5;   // warp id 0..1023
    int lane = threadIdx.x & 31;
    const float* P0 = g_part;
    const float* P1 = g_part + (size_t)NN * DOUT;
    for (int w = w0; w < NN; w += 1024) {
        float4 p0 = *(const float4*)(P0 + (size_t)w * DOUT + lane * 4);
        float4 p1 = *(const float4*)(P1 + (size_t)w * DOUT + lane * 4);
        float4 x4 = {p0.x + p1.x, p0.y + p1.y, p0.z + p1.z, p0.w + p1.w};
        *(float4*)(X + (size_t)w * DOUT + lane * 4) = x4;
        float t = x4.x * x4.x + x4.y * x4.y + x4.z * x4.z + x4.w * x4.w;
#pragma unroll
        for (int o = 16; o; o >>= 1) t += __shfl_down_sync(0xffffffffu, t, o);
        if (lane == 0) g_sq[w] = t;
    }
}

// Phase 1 (pre-sync): warp-level dynamic zero queue — one atomic claim + 16
// coalesced streaming stores per 16KB chunk, no block syncs, so the HBM store
// pipe runs at its floor from t=0 while gemm+combine execute.
// Phase 2 (post gridSync): per-edge score/exp/ssum.
__global__ __launch_bounds__(256) void score_kernel(const float* __restrict__ X,
                                                    const int* __restrict__ edge,
                                                    const float* __restrict__ a,
                                                    float* __restrict__ A) {
    const int tid  = threadIdx.x;
    const int lane = tid & 31;
    {
        float4* A4 = reinterpret_cast<float4*>(A);
        const float4 z4 = make_float4(0.f, 0.f, 0.f, 0.f);
        for (;;) {
            unsigned c;
            if (lane == 0) c = atomicAdd(&g_zctr, 1);
            c = __shfl_sync(0xffffffffu, c, 0);
            if (c >= NQCHUNK) break;
            float4* dst = A4 + (size_t)c * CHUNK_F4 + lane;
#pragma unroll
            for (int i = 0; i < 32; i++)
                __stcs(dst + i * 32, z4);
        }
    }
#if __CUDA_ARCH__ >= 900
    cudaGridDependencySynchronize();   // wait for combine (X, g_sq) + gemm (ssum/cnt)
#endif

    int e = (int)(blockIdx.x * 8u + (tid >> 5));
    if (e >= EE) return;
    int row = edge[e];
    int col = edge[EE + e];

    float4 xi = *(const float4*)(X + (size_t)row * DOUT + lane * 4);
    float4 xj = *(const float4*)(X + (size_t)col * DOUT + lane * 4);
    float4 av = *(const float4*)(a + lane * 4);

    float t = fmaxf(xi.x * xj.x, 0.0f) * av.x
            + fmaxf(xi.y * xj.y, 0.0f) * av.y
            + fmaxf(xi.z * xj.z, 0.0f) * av.z
            + fmaxf(xi.w * xj.w, 0.0f) * av.w;
#pragma unroll
    for (int o = 16; o; o >>= 1) t += __shfl_down_sync(0xffffffffu, t, o);

    if (lane == 0) {
        // s bounded by ||a||_2 (~1.4) => exp cannot overflow; max-shift redundant.
        float ex = 0.0f;
        if (t > 0.0f) ex = __expf(t * rsqrtf(g_sq[row] * g_sq[col]));
        g_s[e] = ex;
        atomicAdd(&g_ssum[row], ex);
        atomicAdd(&g_cnt[row], 1);
    }
}

// vals = ex / ssum[row] (or 1/cnt); scatter-add into A. 1024 blocks x 2
// edges/thread: higher occupancy for this latency-bound atomic kernel.
// Resets the zero queue for the next graph replay.
__global__ __launch_bounds__(256) void scatter_kernel(const int* __restrict__ edge,
                                                      float* __restrict__ A) {
    if (blockIdx.x == 0 && threadIdx.x == 0) g_zctr = 0;
    int base = blockIdx.x * 512 + threadIdx.x;
    int r0 = edge[base],      r1 = edge[base + 256];
    int c0 = edge[EE + base], c1 = edge[EE + base + 256];
    float e0 = g_s[base], e1 = g_s[base + 256];
    float d0 = g_ssum[r0], d1 = g_ssum[r1];
    float v0 = (d0 > 0.0f) ? (e0 / d0) : (1.0f / (float)g_cnt[r0]);
    float v1 = (d1 > 0.0f) ? (e1 / d1) : (1.0f / (float)g_cnt[r1]);
    atomicAdd(A + (size_t)r0 * NN + c0, v0);
    atomicAdd(A + (size_t)r1 * NN + c1, v1);
}

extern "C" void kernel_launch(void* const* d_in, const int* in_sizes, int n_in,
                              void* d_out, int out_size) {
    const float* In   = (const float*)d_in[0];   // [16384, 256]
    const int*   edge = (const int*)d_in[1];     // [2, 524288]
    const float* W    = (const float*)d_in[2];   // [256, 128]
    const float* a    = (const float*)d_in[3];   // [128, 1]
    float* X = (float*)d_out;                    // [16384, 128]
    float* A = X + X_ELEMS;                      // [16384, 16384]

    gemm_split_kernel<<<256, 256>>>(In, W);

    cudaLaunchAttribute attr[1];
    attr[0].id = cudaLaunchAttributeProgrammaticStreamSerialization;
    attr[0].val.programmaticStreamSerializationAllowed = 1;

    {   // combine: PDL w.r.t. gemm (parks only 128 blocks pre-sync)
        cudaLaunchConfig_t cfg = {};
        cfg.gridDim = dim3(128); cfg.blockDim = dim3(256); cfg.stream = 0;
        cfg.attrs = attr; cfg.numAttrs = 1;
        cudaLaunchKernelEx(&cfg, combine_kernel, X);
    }
    {   // score: PDL w.r.t. combine; zero-queue overlaps gemm+combine
        cudaLaunchConfig_t cfg = {};
        cfg.gridDim = dim3(EE / 8); cfg.blockDim = dim3(256); cfg.stream = 0;
        cfg.attrs = attr; cfg.numAttrs = 1;
        cudaLaunchKernelEx(&cfg, score_kernel, X, edge, a, A);
    }

    scatter_kernel<<<EE / 512, 256>>>(edge, A);
}